// round 6
// baseline (speedup 1.0000x reference)
#include <cuda_runtime.h>
#include <math.h>
#include <stdint.h>

#define BATCH 2
#define TT    2048
#define BT    (BATCH*TT)          // 4096
#define CC    512
#define HH    8
#define HDIM  64
#define LLAY  4
#define VV    50257
#define VPAD  50304               // next multiple of 128
#define FFD   2048
#define LNEPS 1e-5f
#define BHZ   (BATCH*HH)          // 16

// ---------------- scratch (static device memory) -----------------------------
__device__ float g_h   [BT*CC];
__device__ float g_ain [BT*CC];
__device__ float g_qkv [BT*3*CC];
__device__ float g_attn[BT*CC];
__device__ float g_ff  [(size_t)BT*FFD];
__device__ float g_wqkv[(size_t)LLAY*CC*3*CC];
__device__ float g_wp  [(size_t)LLAY*CC*CC];
__device__ float g_w1  [(size_t)LLAY*CC*FFD];
__device__ float g_w2  [(size_t)LLAY*FFD*CC];
__device__ float g_lmw [(size_t)CC*VPAD];           // padded + pre-rounded LM weight
__device__ float g_loss;

// ---------------- helpers ----------------------------------------------------
__device__ __forceinline__ float warpSum(float v) {
    #pragma unroll
    for (int o = 16; o; o >>= 1) v += __shfl_xor_sync(0xffffffffu, v, o);
    return v;
}
__device__ __forceinline__ float tf32r(float x) {
    uint32_t u;
    asm("cvt.rna.tf32.f32 %0, %1;" : "=r"(u) : "f"(x));
    return __uint_as_float(u);
}
__device__ __forceinline__ void mma8(float* c, const uint32_t* a, const uint32_t* b) {
    asm volatile(
        "mma.sync.aligned.m16n8k8.row.col.f32.tf32.tf32.f32 "
        "{%0,%1,%2,%3}, {%4,%5,%6,%7}, {%8,%9}, {%0,%1,%2,%3};"
        : "+f"(c[0]), "+f"(c[1]), "+f"(c[2]), "+f"(c[3])
        : "r"(a[0]), "r"(a[1]), "r"(a[2]), "r"(a[3]), "r"(b[0]), "r"(b[1]));
}
__device__ __forceinline__ uint32_t sptr(const void* p) {
    return (uint32_t)__cvta_generic_to_shared(p);
}
#define CP_ASYNC16(d, s) \
    asm volatile("cp.async.ca.shared.global [%0], [%1], 16;\n" :: "r"(d), "l"(s))
#define CP_COMMIT() asm volatile("cp.async.commit_group;\n" ::: "memory")
#define CP_WAIT2()  asm volatile("cp.async.wait_group 2;\n"  ::: "memory")

// ---------------- fused weight prep -------------------------------------------
// regions: [0, NQKV)            packed qkv  (tf32-rounded)
//          [NQKV, +NWP)         wproj
//          [.., +NW1)           wff1
//          [.., +NW2)           wff2
//          [.., +NLMW)          lm weight transposed-pad [C][VPAD]
#define NQKV (LLAY*CC*3*CC)
#define NWP  (LLAY*CC*CC)
#define NW1  (LLAY*CC*FFD)
#define NW2  (LLAY*FFD*CC)
#define NLMW (CC*VPAD)
#define NPREP (NQKV+NWP+NW1+NW2+NLMW)

__global__ void weight_prep_kernel(const float* __restrict__ wq,
                                   const float* __restrict__ wk,
                                   const float* __restrict__ wv,
                                   const float* __restrict__ wproj,
                                   const float* __restrict__ wff1,
                                   const float* __restrict__ wff2,
                                   const float* __restrict__ lmw) {
    long long i = (long long)blockIdx.x * blockDim.x + threadIdx.x;
    if (i >= NPREP) return;
    if (i < NQKV) {
        int idx = (int)i;
        int j = idx % (3 * CC);
        int c = (idx / (3 * CC)) % CC;
        int l = idx / (3 * CC * CC);
        int which = j / CC;
        int jj = j % CC;
        int h = jj / HDIM, d = jj % HDIM;
        const float* w = (which == 0) ? wq : (which == 1) ? wk : wv;
        g_wqkv[idx] = tf32r(w[(((size_t)l * HH + h) * CC + c) * HDIM + d]);
        return;
    }
    i -= NQKV;
    if (i < NWP)  { g_wp[i] = tf32r(wproj[i]); return; }
    i -= NWP;
    if (i < NW1)  { g_w1[i] = tf32r(wff1[i]); return; }
    i -= NW1;
    if (i < NW2)  { g_w2[i] = tf32r(wff2[i]); return; }
    i -= NW2;
    {
        int v = (int)(i % VPAD), c = (int)(i / VPAD);
        g_lmw[i] = (v < VV) ? tf32r(lmw[(size_t)c * VV + v]) : 0.f;
    }
}

// ---------------- embedding ---------------------------------------------------
__global__ void embed_kernel(const int* __restrict__ x,
                             const float* __restrict__ tok,
                             const float* __restrict__ pos) {
    int i = blockIdx.x * blockDim.x + threadIdx.x;
    if (i >= BT * CC) return;
    int c  = i % CC;
    int bt = i / CC;
    int t  = bt % TT;
    g_h[i] = tok[(size_t)x[bt] * CC + c] + pos[(size_t)t * CC + c];
}

// ---------------- layernorm (outputs tf32-rounded: feeds GEMM A) -------------
__global__ void ln_kernel(const float* __restrict__ in,
                          const float* __restrict__ sc,
                          const float* __restrict__ bi,
                          float* __restrict__ out) {
    int row = blockIdx.x, tid = threadIdx.x;
    const float* r = in + (size_t)row * CC;
    float a = r[tid], b = r[tid + 256];
    float s = a + b, q = a * a + b * b;
    s = warpSum(s); q = warpSum(q);
    __shared__ float rs[8], rq[8];
    if ((tid & 31) == 0) { rs[tid >> 5] = s; rq[tid >> 5] = q; }
    __syncthreads();
    __shared__ float s_mean, s_rstd;
    if (tid == 0) {
        float S = 0.f, Q = 0.f;
        #pragma unroll
        for (int i = 0; i < 8; i++) { S += rs[i]; Q += rq[i]; }
        float m = S * (1.0f / CC);
        float v = Q * (1.0f / CC) - m * m;
        s_mean = m; s_rstd = rsqrtf(v + LNEPS);
    }
    __syncthreads();
    float m = s_mean, rstd = s_rstd;
    float* o = out + (size_t)row * CC;
    o[tid]       = tf32r((a - m) * rstd * sc[tid]       + bi[tid]);
    o[tid + 256] = tf32r((b - m) * rstd * sc[tid + 256] + bi[tid + 256]);
}

// ---------------- tf32 GEMM: C = A[M,K] @ B[K,ldB], 4-stage cp.async ---------
// 128x128 tile, BK=16, 256 threads (8 warps 2x4, 64x32 each). One sync/iter.
#define AS_STRIDE (128*20)
#define BS_STRIDE (16*136)
#define GSMEM (4*(AS_STRIDE+BS_STRIDE)*4)   // 75776 bytes

__global__ __launch_bounds__(256, 2)
void gemm_tf32_kernel(const float* __restrict__ A,
                      const float* __restrict__ B,
                      float* __restrict__ Cout,
                      int M, int N, int K, int ldB,
                      const float* __restrict__ bias,
                      const float* __restrict__ res,
                      int relu, int rndout) {
    extern __shared__ __align__(16) float dsm[];
    float* Asf = dsm;                     // [4][128][20]
    float* Bsf = dsm + 4 * AS_STRIDE;     // [4][16][136]

    int tid = threadIdx.x;
    int row0 = blockIdx.y * 128, col0 = blockIdx.x * 128;

    int lane = tid & 31, gid = lane >> 2, tig = lane & 3;
    int wid = tid >> 5;
    int wr = (wid >> 2) * 64;
    int wc = (wid & 3) * 32;

    float acc[4][4][4];
    #pragma unroll
    for (int i = 0; i < 4; i++)
        #pragma unroll
        for (int j = 0; j < 4; j++)
            #pragma unroll
            for (int q = 0; q < 4; q++) acc[i][j][q] = 0.f;

    int arr0 = (tid) >> 2,        akc0 = ((tid) & 3) << 2;
    int arr1 = (tid + 256) >> 2,  akc1 = ((tid + 256) & 3) << 2;
    int brr0 = (tid) >> 5,        bcc0 = ((tid) & 31) << 2;
    int brr1 = (tid + 256) >> 5,  bcc1 = ((tid + 256) & 31) << 2;

    const float* Abase = A + (size_t)row0 * K;
    const float* Bbase = B + col0;

    #define LOAD_STAGE(st, k0)                                                   \
        do {                                                                     \
            float* as = Asf + (st) * AS_STRIDE;                                  \
            float* bs = Bsf + (st) * BS_STRIDE;                                  \
            CP_ASYNC16(sptr(as + arr0 * 20 + akc0),                              \
                       Abase + (size_t)arr0 * K + (k0) + akc0);                  \
            CP_ASYNC16(sptr(as + arr1 * 20 + akc1),                              \
                       Abase + (size_t)arr1 * K + (k0) + akc1);                  \
            CP_ASYNC16(sptr(bs + brr0 * 136 + bcc0),                             \
                       Bbase + (size_t)((k0) + brr0) * ldB + bcc0);              \
            CP_ASYNC16(sptr(bs + brr1 * 136 + bcc1),                             \
                       Bbase + (size_t)((k0) + brr1) * ldB + bcc1);              \
        } while (0)

    int ntiles = K >> 4;
    #pragma unroll
    for (int s = 0; s < 3; s++) {
        if (s < ntiles) LOAD_STAGE(s, s << 4);
        CP_COMMIT();
    }

    for (int it = 0; it < ntiles; it++) {
        CP_WAIT2();
        __syncthreads();
        int nx = it + 3;
        if (nx < ntiles) LOAD_STAGE(nx & 3, nx << 4);
        CP_COMMIT();

        const float* as = Asf + (it & 3) * AS_STRIDE;
        const float* bs = Bsf + (it & 3) * BS_STRIDE;
        #pragma unroll
        for (int kb = 0; kb < 16; kb += 8) {
            uint32_t af[4][4], bf[4][2];
            #pragma unroll
            for (int i = 0; i < 4; i++) {
                int m = wr + i * 16 + gid;
                af[i][0] = __float_as_uint(as[(m    ) * 20 + kb + tig    ]);
                af[i][1] = __float_as_uint(as[(m + 8) * 20 + kb + tig    ]);
                af[i][2] = __float_as_uint(as[(m    ) * 20 + kb + tig + 4]);
                af[i][3] = __float_as_uint(as[(m + 8) * 20 + kb + tig + 4]);
            }
            #pragma unroll
            for (int j = 0; j < 4; j++) {
                int n = wc + j * 8 + gid;
                bf[j][0] = __float_as_uint(bs[(kb + tig    ) * 136 + n]);
                bf[j][1] = __float_as_uint(bs[(kb + tig + 4) * 136 + n]);
            }
            #pragma unroll
            for (int i = 0; i < 4; i++)
                #pragma unroll
                for (int j = 0; j < 4; j++)
                    mma8(acc[i][j], af[i], bf[j]);
        }
    }
    #undef LOAD_STAGE

    #pragma unroll
    for (int i = 0; i < 4; i++)
        #pragma unroll
        for (int j = 0; j < 4; j++) {
            int c0 = col0 + wc + j * 8 + tig * 2;
            #pragma unroll
            for (int h2 = 0; h2 < 2; h2++) {
                int r = row0 + wr + i * 16 + gid + h2 * 8;
                float v0 = acc[i][j][h2 * 2 + 0];
                float v1 = acc[i][j][h2 * 2 + 1];
                if (c0 < N) {
                    if (bias) v0 += bias[c0];
                    if (res)  v0 += res[(size_t)r * N + c0];
                    if (relu) v0 = fmaxf(v0, 0.f);
                    if (rndout) v0 = tf32r(v0);
                    Cout[(size_t)r * N + c0] = v0;
                }
                if (c0 + 1 < N) {
                    if (bias) v1 += bias[c0 + 1];
                    if (res)  v1 += res[(size_t)r * N + c0 + 1];
                    if (relu) v1 = fmaxf(v1, 0.f);
                    if (rndout) v1 = tf32r(v1);
                    Cout[(size_t)r * N + c0 + 1] = v1;
                }
            }
        }
}

// ---------------- fused flash attention --------------------------------------
#define FBQ 128
#define FBS 64
#define KLD 68
#define VLD 72
#define PLD 136
#define FSMEM ((FBS*KLD + FBS*VLD + FBS*PLD) * 4)   // 70656 bytes

__global__ __launch_bounds__(256, 1)
void flash_kernel(const float* __restrict__ qkv, float* __restrict__ outp) {
    extern __shared__ float fsm[];
    float* Ks = fsm;                       // [s][KLD]
    float* Vs = fsm + FBS * KLD;           // [s][VLD]
    float* Ps = fsm + FBS * (KLD + VLD);   // [s][PLD]

    int tid = threadIdx.x;
    int lane = tid & 31, gid = lane >> 2, tig = lane & 3;
    int wid = tid >> 5;
    int wrow = wid * 16;
    int q0 = (gridDim.x - 1 - blockIdx.x) * FBQ;   // heavy tiles first
    int z = blockIdx.y;
    int b = z >> 3, h = z & 7;
    const float* qbase = qkv + (size_t)b * TT * (3 * CC) + h * HDIM;
    const float* kbase = qbase + CC;
    const float* vbase = qbase + 2 * CC;

    uint32_t aQ[8][4];
    {
        int t0 = q0 + wrow + gid;
        const float* q0p = qbase + (size_t)t0 * (3 * CC);
        const float* q1p = q0p + 8 * (3 * CC);
        #pragma unroll
        for (int ks = 0; ks < 8; ks++) {
            aQ[ks][0] = __float_as_uint(q0p[ks * 8 + tig]);
            aQ[ks][1] = __float_as_uint(q1p[ks * 8 + tig]);
            aQ[ks][2] = __float_as_uint(q0p[ks * 8 + tig + 4]);
            aQ[ks][3] = __float_as_uint(q1p[ks * 8 + tig + 4]);
        }
    }

    float oAcc[8][4];
    #pragma unroll
    for (int j = 0; j < 8; j++)
        #pragma unroll
        for (int q = 0; q < 4; q++) oAcc[j][q] = 0.f;
    float m0 = -1e30f, m1 = -1e30f, l0 = 0.f, l1 = 0.f;

    int t0g = q0 + wrow + gid, t1g = t0g + 8;
    int nTiles = q0 / FBS + 2;

    for (int it = 0; it < nTiles; it++) {
        int s0 = it * FBS;
        __syncthreads();
        #pragma unroll
        for (int i = 0; i < 4; i++) {
            int f4 = tid + i * 256;
            int r = f4 >> 4, kc = (f4 & 15) << 2;
            float4 kv = *reinterpret_cast<const float4*>(
                kbase + (size_t)(s0 + r) * (3 * CC) + kc);
            *reinterpret_cast<float4*>(Ks + r * KLD + kc) = kv;
            float4 vv = *reinterpret_cast<const float4*>(
                vbase + (size_t)(s0 + r) * (3 * CC) + kc);
            *reinterpret_cast<float4*>(Vs + r * VLD + kc) = vv;
        }
        __syncthreads();

        float sAcc[8][4];
        #pragma unroll
        for (int j = 0; j < 8; j++)
            #pragma unroll
            for (int q = 0; q < 4; q++) sAcc[j][q] = 0.f;
        #pragma unroll
        for (int ks = 0; ks < 8; ks++) {
            int kb = ks * 8;
            #pragma unroll
            for (int j = 0; j < 8; j++) {
                int n = j * 8 + gid;
                uint32_t bb[2];
                bb[0] = __float_as_uint(Ks[n * KLD + kb + tig]);
                bb[1] = __float_as_uint(Ks[n * KLD + kb + tig + 4]);
                mma8(sAcc[j], aQ[ks], bb);
            }
        }

        #pragma unroll
        for (int j = 0; j < 8; j++) {
            int sb = s0 + j * 8 + tig * 2;
            #pragma unroll
            for (int q = 0; q < 4; q++) {
                float v = sAcc[j][q] * 0.125f;
                int s_g = sb + (q & 1);
                int t_g = (q < 2) ? t0g : t1g;
                sAcc[j][q] = (s_g > t_g) ? -1e30f : v;
            }
        }

        float rm0 = -1e30f, rm1 = -1e30f;
        #pragma unroll
        for (int j = 0; j < 8; j++) {
            rm0 = fmaxf(rm0, fmaxf(sAcc[j][0], sAcc[j][1]));
            rm1 = fmaxf(rm1, fmaxf(sAcc[j][2], sAcc[j][3]));
        }
        #pragma unroll
        for (int o = 1; o <= 2; o <<= 1) {
            rm0 = fmaxf(rm0, __shfl_xor_sync(0xffffffffu, rm0, o));
            rm1 = fmaxf(rm1, __shfl_xor_sync(0xffffffffu, rm1, o));
        }
        float nm0 = fmaxf(m0, rm0), nm1 = fmaxf(m1, rm1);
        float a0 = __expf(m0 - nm0), a1 = __expf(m1 - nm1);

        float rs0 = 0.f, rs1 = 0.f;
        #pragma unroll
        for (int j = 0; j < 8; j++) {
            int sb = (j * 8 + tig * 2) * PLD;
            float p0 = __expf(sAcc[j][0] - nm0);
            float p1 = __expf(sAcc[j][1] - nm0);
            float p2 = __expf(sAcc[j][2] - nm1);
            float p3 = __expf(sAcc[j][3] - nm1);
            rs0 += p0 + p1; rs1 += p2 + p3;
            int tc0 = wrow + gid, tc1 = tc0 + 8;
            Ps[sb       + tc0] = tf32r(p0);
            Ps[sb + PLD + tc0] = tf32r(p1);
            Ps[sb       + tc1] = tf32r(p2);
            Ps[sb + PLD + tc1] = tf32r(p3);
        }
        #pragma unroll
        for (int o = 1; o <= 2; o <<= 1) {
            rs0 += __shfl_xor_sync(0xffffffffu, rs0, o);
            rs1 += __shfl_xor_sync(0xffffffffu, rs1, o);
        }
        l0 = l0 * a0 + rs0;
        l1 = l1 * a1 + rs1;
        m0 = nm0; m1 = nm1;

        #pragma unroll
        for (int j = 0; j < 8; j++) {
            oAcc[j][0] *= a0; oAcc[j][1] *= a0;
            oAcc[j][2] *= a1; oAcc[j][3] *= a1;
        }
        __syncwarp();

        #pragma unroll
        for (int ks = 0; ks < 8; ks++) {
            int kb = ks * 8;
            uint32_t aP[4];
            int mr = wrow + gid;
            aP[0] = __float_as_uint(Ps[(kb + tig    ) * PLD + mr    ]);
            aP[1] = __float_as_uint(Ps[(kb + tig    ) * PLD + mr + 8]);
            aP[2] = __float_as_uint(Ps[(kb + tig + 4) * PLD + mr    ]);
            aP[3] = __float_as_uint(Ps[(kb + tig + 4) * PLD + mr + 8]);
            #pragma unroll
            for (int j = 0; j < 8; j++) {
                int n = j * 8 + gid;
                uint32_t bb[2];
                bb[0] = __float_as_uint(Vs[(kb + tig    ) * VLD + n]);
                bb[1] = __float_as_uint(Vs[(kb + tig + 4) * VLD + n]);
                mma8(oAcc[j], aP, bb);
            }
        }
    }

    float inv0 = 1.f / l0, inv1 = 1.f / l1;
    float* o0 = outp + (size_t)(b * TT + t0g) * CC + h * HDIM;
    float* o1 = outp + (size_t)(b * TT + t1g) * CC + h * HDIM;
    #pragma unroll
    for (int j = 0; j < 8; j++) {
        int d = j * 8 + tig * 2;
        o0[d]     = tf32r(oAcc[j][0] * inv0);
        o0[d + 1] = tf32r(oAcc[j][1] * inv0);
        o1[d]     = tf32r(oAcc[j][2] * inv1);
        o1[d + 1] = tf32r(oAcc[j][3] * inv1);
    }
}

// ---------------- loss: single-pass online logsumexp (alignment-safe) --------
__global__ void zero_loss_kernel() { g_loss = 0.f; }

__global__ void loss_kernel(const float* __restrict__ logits,
                            const int* __restrict__ target) {
    int row = blockIdx.x, tid = threadIdx.x;
    const float* lr = logits + (size_t)row * VV;
    float m = -1e30f, s = 0.f;

    int head = (int)(((16u - ((uintptr_t)lr & 15u)) & 15u) >> 2);
    if (head > VV) head = VV;
    for (int i = tid; i < head; i += 256) {
        float v = lr[i];
        if (v > m) { s = s * __expf(m - v); m = v; }
        s += __expf(v - m);
    }
    const float* lra = lr + head;
    int nrem = VV - head;
    int n4 = nrem >> 2;
    for (int i4 = tid; i4 < n4; i4 += 256) {
        float4 v = *reinterpret_cast<const float4*>(lra + i4 * 4);
        float vm = fmaxf(fmaxf(v.x, v.y), fmaxf(v.z, v.w));
        if (vm > m) { s = s * __expf(m - vm); m = vm; }
        s += __expf(v.x - m) + __expf(v.y - m) + __expf(v.z - m) + __expf(v.w - m);
    }
    for (int i = head + n4 * 4 + tid; i < VV; i += 256) {
        float v = lr[i];
        if (v > m) { s = s * __expf(m - v); m = v; }
        s += __expf(v - m);
    }
    #pragma unroll
    for (int o = 16; o; o >>= 1) {
        float mo = __shfl_xor_sync(0xffffffffu, m, o);
        float so = __shfl_xor_sync(0xffffffffu, s, o);
        float M = fmaxf(m, mo);
        s = s * __expf(m - M) + so * __expf(mo - M);
        m = M;
    }
    __shared__ float rm[8], rs[8];
    if ((tid & 31) == 0) { rm[tid >> 5] = m; rs[tid >> 5] = s; }
    __syncthreads();
    if (tid == 0) {
        float M = rm[0];
        #pragma unroll
        for (int i = 1; i < 8; i++) M = fmaxf(M, rm[i]);
        float S = 0.f;
        #pragma unroll
        for (int i = 0; i < 8; i++) S += rs[i] * __expf(rm[i] - M);
        float lse = M + logf(S);
        atomicAdd(&g_loss, lse - lr[target[row]]);
    }
}

__global__ void finalize_loss_kernel(float* __restrict__ out) {
    out[(size_t)BT * VV] = g_loss * (1.0f / BT);
}

// ---------------- launch ------------------------------------------------------
extern "C" void kernel_launch(void* const* d_in, const int* in_sizes, int n_in,
                              void* d_out, int out_size) {
    const int*   x      = (const int*)  d_in[0];
    const int*   target = (const int*)  d_in[1];
    const float* tok    = (const float*)d_in[2];
    const float* pos    = (const float*)d_in[3];
    const float* ln1s   = (const float*)d_in[4];
    const float* ln1b   = (const float*)d_in[5];
    const float* wq     = (const float*)d_in[6];
    const float* wk     = (const float*)d_in[7];
    const float* wv     = (const float*)d_in[8];
    const float* wproj  = (const float*)d_in[9];
    const float* bproj  = (const float*)d_in[10];
    const float* ln2s   = (const float*)d_in[11];
    const float* ln2b   = (const float*)d_in[12];
    const float* wff1   = (const float*)d_in[13];
    const float* bff1   = (const float*)d_in[14];
    const float* wff2   = (const float*)d_in[15];
    const float* bff2   = (const float*)d_in[16];
    const float* lnfs   = (const float*)d_in[17];
    const float* lnfb   = (const float*)d_in[18];
    const float* lmw    = (const float*)d_in[19];
    const float* lmb    = (const float*)d_in[20];
    float* out = (float*)d_out;

    float *p_h, *p_ain, *p_qkv, *p_attn, *p_ff, *p_wqkv, *p_wp, *p_w1, *p_w2,
          *p_lmw;
    cudaGetSymbolAddress((void**)&p_h,    g_h);
    cudaGetSymbolAddress((void**)&p_ain,  g_ain);
    cudaGetSymbolAddress((void**)&p_qkv,  g_qkv);
    cudaGetSymbolAddress((void**)&p_attn, g_attn);
    cudaGetSymbolAddress((void**)&p_ff,   g_ff);
    cudaGetSymbolAddress((void**)&p_wqkv, g_wqkv);
    cudaGetSymbolAddress((void**)&p_wp,   g_wp);
    cudaGetSymbolAddress((void**)&p_w1,   g_w1);
    cudaGetSymbolAddress((void**)&p_w2,   g_w2);
    cudaGetSymbolAddress((void**)&p_lmw,  g_lmw);

    static int attr_done = 0;
    if (!attr_done) {
        cudaFuncSetAttribute(flash_kernel,
                             cudaFuncAttributeMaxDynamicSharedMemorySize, FSMEM);
        cudaFuncSetAttribute(gemm_tf32_kernel,
                             cudaFuncAttributeMaxDynamicSharedMemorySize, GSMEM);
        attr_done = 1;
    }

    weight_prep_kernel<<<(int)((NPREP + 255) / 256), 256>>>(
        wq, wk, wv, wproj, wff1, wff2, lmw);
    embed_kernel<<<(BT * CC + 255) / 256, 256>>>(x, tok, pos);

    dim3 gQKV((3 * CC) / 128, BT / 128);
    dim3 gC  (CC / 128,       BT / 128);
    dim3 gFF (FFD / 128,      BT / 128);
    dim3 gV  (VPAD / 128,     BT / 128);
    dim3 gFA (TT / FBQ, BHZ);

    for (int l = 0; l < LLAY; l++) {
        ln_kernel<<<BT, 256>>>(p_h, ln1s + l * CC, ln1b + l * CC, p_ain);
        gemm_tf32_kernel<<<gQKV, 256, GSMEM>>>(
            p_ain, p_wqkv + (size_t)l * CC * 3 * CC, p_qkv,
            BT, 3 * CC, CC, 3 * CC, nullptr, nullptr, 0, 1);
        flash_kernel<<<gFA, 256, FSMEM>>>(p_qkv, p_attn);
        gemm_tf32_kernel<<<gC, 256, GSMEM>>>(
            p_attn, p_wp + (size_t)l * CC * CC, p_h,
            BT, CC, CC, CC, bproj + l * CC, p_h, 0, 0);
        ln_kernel<<<BT, 256>>>(p_h, ln2s + l * CC, ln2b + l * CC, p_ain);
        gemm_tf32_kernel<<<gFF, 256, GSMEM>>>(
            p_ain, p_w1 + (size_t)l * CC * FFD, p_ff,
            BT, FFD, CC, FFD, bff1 + l * FFD, nullptr, 1, 1);
        gemm_tf32_kernel<<<gC, 256, GSMEM>>>(
            p_ff, p_w2 + (size_t)l * FFD * CC, p_h,
            BT, CC, FFD, CC, bff2 + l * CC, p_h, 0, 0);
    }

    ln_kernel<<<BT, 256>>>(p_h, lnfs, lnfb, p_ain);
    gemm_tf32_kernel<<<gV, 256, GSMEM>>>(
        p_ain, p_lmw, out, BT, VV, CC, VPAD, lmb, nullptr, 0, 0);

    if ((long long)out_size > (long long)BT * VV) {
        zero_loss_kernel<<<1, 1>>>();
        loss_kernel<<<BT, 256>>>(out, target);
        finalize_loss_kernel<<<1, 1>>>(out);
    }
}

// round 7
// speedup vs baseline: 1.0016x; 1.0016x over previous
#include <cuda_runtime.h>
#include <math.h>
#include <stdint.h>

#define BATCH 2
#define TT    2048
#define BT    (BATCH*TT)          // 4096
#define CC    512
#define HH    8
#define HDIM  64
#define LLAY  4
#define VV    50257
#define VPAD  50304               // next multiple of 128
#define FFD   2048
#define LNEPS 1e-5f
#define BHZ   (BATCH*HH)          // 16

// ---------------- scratch (static device memory) -----------------------------
__device__ float g_h   [BT*CC];
__device__ float g_ain [BT*CC];
__device__ float g_qkv [BT*3*CC];
__device__ float g_attn[BT*CC];
__device__ float g_ff  [(size_t)BT*FFD];
__device__ float g_wqkv[(size_t)LLAY*CC*3*CC];
__device__ float g_wp  [(size_t)LLAY*CC*CC];
__device__ float g_w1  [(size_t)LLAY*CC*FFD];
__device__ float g_w2  [(size_t)LLAY*FFD*CC];
__device__ float g_lmw [(size_t)CC*VPAD];           // padded + pre-rounded LM weight
__device__ float g_loss;

// ---------------- helpers ----------------------------------------------------
__device__ __forceinline__ float warpSum(float v) {
    #pragma unroll
    for (int o = 16; o; o >>= 1) v += __shfl_xor_sync(0xffffffffu, v, o);
    return v;
}
__device__ __forceinline__ float tf32r(float x) {
    uint32_t u;
    asm("cvt.rna.tf32.f32 %0, %1;" : "=r"(u) : "f"(x));
    return __uint_as_float(u);
}
__device__ __forceinline__ void mma8(float* c, const uint32_t* a, const uint32_t* b) {
    asm volatile(
        "mma.sync.aligned.m16n8k8.row.col.f32.tf32.tf32.f32 "
        "{%0,%1,%2,%3}, {%4,%5,%6,%7}, {%8,%9}, {%0,%1,%2,%3};"
        : "+f"(c[0]), "+f"(c[1]), "+f"(c[2]), "+f"(c[3])
        : "r"(a[0]), "r"(a[1]), "r"(a[2]), "r"(a[3]), "r"(b[0]), "r"(b[1]));
}
__device__ __forceinline__ uint32_t sptr(const void* p) {
    return (uint32_t)__cvta_generic_to_shared(p);
}
#define CP_ASYNC16(d, s) \
    asm volatile("cp.async.ca.shared.global [%0], [%1], 16;\n" :: "r"(d), "l"(s))
#define CP_COMMIT() asm volatile("cp.async.commit_group;\n" ::: "memory")
#define CP_WAIT2()  asm volatile("cp.async.wait_group 2;\n"  ::: "memory")

// ---------------- fused weight prep -------------------------------------------
// regions: [0, NQKV)            packed qkv  (tf32-rounded)
//          [NQKV, +NWP)         wproj
//          [.., +NW1)           wff1
//          [.., +NW2)           wff2
//          [.., +NLMW)          lm weight transposed-pad [C][VPAD]
#define NQKV (LLAY*CC*3*CC)
#define NWP  (LLAY*CC*CC)
#define NW1  (LLAY*CC*FFD)
#define NW2  (LLAY*FFD*CC)
#define NLMW (CC*VPAD)
#define NPREP (NQKV+NWP+NW1+NW2+NLMW)

__global__ void weight_prep_kernel(const float* __restrict__ wq,
                                   const float* __restrict__ wk,
                                   const float* __restrict__ wv,
                                   const float* __restrict__ wproj,
                                   const float* __restrict__ wff1,
                                   const float* __restrict__ wff2,
                                   const float* __restrict__ lmw) {
    long long i = (long long)blockIdx.x * blockDim.x + threadIdx.x;
    if (i >= NPREP) return;
    if (i < NQKV) {
        int idx = (int)i;
        int j = idx % (3 * CC);
        int c = (idx / (3 * CC)) % CC;
        int l = idx / (3 * CC * CC);
        int which = j / CC;
        int jj = j % CC;
        int h = jj / HDIM, d = jj % HDIM;
        const float* w = (which == 0) ? wq : (which == 1) ? wk : wv;
        g_wqkv[idx] = tf32r(w[(((size_t)l * HH + h) * CC + c) * HDIM + d]);
        return;
    }
    i -= NQKV;
    if (i < NWP)  { g_wp[i] = tf32r(wproj[i]); return; }
    i -= NWP;
    if (i < NW1)  { g_w1[i] = tf32r(wff1[i]); return; }
    i -= NW1;
    if (i < NW2)  { g_w2[i] = tf32r(wff2[i]); return; }
    i -= NW2;
    {
        int v = (int)(i % VPAD), c = (int)(i / VPAD);
        g_lmw[i] = (v < VV) ? tf32r(lmw[(size_t)c * VV + v]) : 0.f;
    }
}

// ---------------- embedding ---------------------------------------------------
__global__ void embed_kernel(const int* __restrict__ x,
                             const float* __restrict__ tok,
                             const float* __restrict__ pos) {
    int i = blockIdx.x * blockDim.x + threadIdx.x;
    if (i >= BT * CC) return;
    int c  = i % CC;
    int bt = i / CC;
    int t  = bt % TT;
    g_h[i] = tok[(size_t)x[bt] * CC + c] + pos[(size_t)t * CC + c];
}

// ---------------- layernorm (outputs tf32-rounded: feeds GEMM A) -------------
__global__ void ln_kernel(const float* __restrict__ in,
                          const float* __restrict__ sc,
                          const float* __restrict__ bi,
                          float* __restrict__ out) {
    int row = blockIdx.x, tid = threadIdx.x;
    const float* r = in + (size_t)row * CC;
    float a = r[tid], b = r[tid + 256];
    float s = a + b, q = a * a + b * b;
    s = warpSum(s); q = warpSum(q);
    __shared__ float rs[8], rq[8];
    if ((tid & 31) == 0) { rs[tid >> 5] = s; rq[tid >> 5] = q; }
    __syncthreads();
    __shared__ float s_mean, s_rstd;
    if (tid == 0) {
        float S = 0.f, Q = 0.f;
        #pragma unroll
        for (int i = 0; i < 8; i++) { S += rs[i]; Q += rq[i]; }
        float m = S * (1.0f / CC);
        float v = Q * (1.0f / CC) - m * m;
        s_mean = m; s_rstd = rsqrtf(v + LNEPS);
    }
    __syncthreads();
    float m = s_mean, rstd = s_rstd;
    float* o = out + (size_t)row * CC;
    o[tid]       = tf32r((a - m) * rstd * sc[tid]       + bi[tid]);
    o[tid + 256] = tf32r((b - m) * rstd * sc[tid + 256] + bi[tid + 256]);
}

// ---------------- tf32 GEMM: C = A[M,K] @ B[K,ldB], 4-stage cp.async ---------
// 128x128 tile, BK=16, 256 threads (8 warps 2x4, 64x32 each). One sync/iter.
#define AS_STRIDE (128*20)
#define BS_STRIDE (16*136)
#define GSMEM (4*(AS_STRIDE+BS_STRIDE)*4)   // 75776 bytes

__global__ __launch_bounds__(256, 2)
void gemm_tf32_kernel(const float* __restrict__ A,
                      const float* __restrict__ B,
                      float* __restrict__ Cout,
                      int M, int N, int K, int ldB,
                      const float* __restrict__ bias,
                      const float* __restrict__ res,
                      int relu, int rndout) {
    extern __shared__ __align__(16) float dsm[];
    float* Asf = dsm;                     // [4][128][20]
    float* Bsf = dsm + 4 * AS_STRIDE;     // [4][16][136]

    int tid = threadIdx.x;
    int row0 = blockIdx.y * 128, col0 = blockIdx.x * 128;

    int lane = tid & 31, gid = lane >> 2, tig = lane & 3;
    int wid = tid >> 5;
    int wr = (wid >> 2) * 64;
    int wc = (wid & 3) * 32;

    float acc[4][4][4];
    #pragma unroll
    for (int i = 0; i < 4; i++)
        #pragma unroll
        for (int j = 0; j < 4; j++)
            #pragma unroll
            for (int q = 0; q < 4; q++) acc[i][j][q] = 0.f;

    int arr0 = (tid) >> 2,        akc0 = ((tid) & 3) << 2;
    int arr1 = (tid + 256) >> 2,  akc1 = ((tid + 256) & 3) << 2;
    int brr0 = (tid) >> 5,        bcc0 = ((tid) & 31) << 2;
    int brr1 = (tid + 256) >> 5,  bcc1 = ((tid + 256) & 31) << 2;

    const float* Abase = A + (size_t)row0 * K;
    const float* Bbase = B + col0;

    #define LOAD_STAGE(st, k0)                                                   \
        do {                                                                     \
            float* as = Asf + (st) * AS_STRIDE;                                  \
            float* bs = Bsf + (st) * BS_STRIDE;                                  \
            CP_ASYNC16(sptr(as + arr0 * 20 + akc0),                              \
                       Abase + (size_t)arr0 * K + (k0) + akc0);                  \
            CP_ASYNC16(sptr(as + arr1 * 20 + akc1),                              \
                       Abase + (size_t)arr1 * K + (k0) + akc1);                  \
            CP_ASYNC16(sptr(bs + brr0 * 136 + bcc0),                             \
                       Bbase + (size_t)((k0) + brr0) * ldB + bcc0);              \
            CP_ASYNC16(sptr(bs + brr1 * 136 + bcc1),                             \
                       Bbase + (size_t)((k0) + brr1) * ldB + bcc1);              \
        } while (0)

    int ntiles = K >> 4;
    #pragma unroll
    for (int s = 0; s < 3; s++) {
        if (s < ntiles) LOAD_STAGE(s, s << 4);
        CP_COMMIT();
    }

    for (int it = 0; it < ntiles; it++) {
        CP_WAIT2();
        __syncthreads();
        int nx = it + 3;
        if (nx < ntiles) LOAD_STAGE(nx & 3, nx << 4);
        CP_COMMIT();

        const float* as = Asf + (it & 3) * AS_STRIDE;
        const float* bs = Bsf + (it & 3) * BS_STRIDE;
        #pragma unroll
        for (int kb = 0; kb < 16; kb += 8) {
            uint32_t af[4][4], bf[4][2];
            #pragma unroll
            for (int i = 0; i < 4; i++) {
                int m = wr + i * 16 + gid;
                af[i][0] = __float_as_uint(as[(m    ) * 20 + kb + tig    ]);
                af[i][1] = __float_as_uint(as[(m + 8) * 20 + kb + tig    ]);
                af[i][2] = __float_as_uint(as[(m    ) * 20 + kb + tig + 4]);
                af[i][3] = __float_as_uint(as[(m + 8) * 20 + kb + tig + 4]);
            }
            #pragma unroll
            for (int j = 0; j < 4; j++) {
                int n = wc + j * 8 + gid;
                bf[j][0] = __float_as_uint(bs[(kb + tig    ) * 136 + n]);
                bf[j][1] = __float_as_uint(bs[(kb + tig + 4) * 136 + n]);
            }
            #pragma unroll
            for (int i = 0; i < 4; i++)
                #pragma unroll
                for (int j = 0; j < 4; j++)
                    mma8(acc[i][j], af[i], bf[j]);
        }
    }
    #undef LOAD_STAGE

    #pragma unroll
    for (int i = 0; i < 4; i++)
        #pragma unroll
        for (int j = 0; j < 4; j++) {
            int c0 = col0 + wc + j * 8 + tig * 2;
            #pragma unroll
            for (int h2 = 0; h2 < 2; h2++) {
                int r = row0 + wr + i * 16 + gid + h2 * 8;
                float v0 = acc[i][j][h2 * 2 + 0];
                float v1 = acc[i][j][h2 * 2 + 1];
                if (c0 < N) {
                    if (bias) v0 += bias[c0];
                    if (res)  v0 += res[(size_t)r * N + c0];
                    if (relu) v0 = fmaxf(v0, 0.f);
                    if (rndout) v0 = tf32r(v0);
                    Cout[(size_t)r * N + c0] = v0;
                }
                if (c0 + 1 < N) {
                    if (bias) v1 += bias[c0 + 1];
                    if (res)  v1 += res[(size_t)r * N + c0 + 1];
                    if (relu) v1 = fmaxf(v1, 0.f);
                    if (rndout) v1 = tf32r(v1);
                    Cout[(size_t)r * N + c0 + 1] = v1;
                }
            }
        }
}

// ---------------- fused flash attention --------------------------------------
#define FBQ 128
#define FBS 64
#define KLD 68
#define VLD 72
#define PLD 136
#define FSMEM ((FBS*KLD + FBS*VLD + FBS*PLD) * 4)   // 70656 bytes

__global__ __launch_bounds__(256, 1)
void flash_kernel(const float* __restrict__ qkv, float* __restrict__ outp) {
    extern __shared__ float fsm[];
    float* Ks = fsm;                       // [s][KLD]
    float* Vs = fsm + FBS * KLD;           // [s][VLD]
    float* Ps = fsm + FBS * (KLD + VLD);   // [s][PLD]

    int tid = threadIdx.x;
    int lane = tid & 31, gid = lane >> 2, tig = lane & 3;
    int wid = tid >> 5;
    int wrow = wid * 16;
    int q0 = (gridDim.x - 1 - blockIdx.x) * FBQ;   // heavy tiles first
    int z = blockIdx.y;
    int b = z >> 3, h = z & 7;
    const float* qbase = qkv + (size_t)b * TT * (3 * CC) + h * HDIM;
    const float* kbase = qbase + CC;
    const float* vbase = qbase + 2 * CC;

    uint32_t aQ[8][4];
    {
        int t0 = q0 + wrow + gid;
        const float* q0p = qbase + (size_t)t0 * (3 * CC);
        const float* q1p = q0p + 8 * (3 * CC);
        #pragma unroll
        for (int ks = 0; ks < 8; ks++) {
            aQ[ks][0] = __float_as_uint(q0p[ks * 8 + tig]);
            aQ[ks][1] = __float_as_uint(q1p[ks * 8 + tig]);
            aQ[ks][2] = __float_as_uint(q0p[ks * 8 + tig + 4]);
            aQ[ks][3] = __float_as_uint(q1p[ks * 8 + tig + 4]);
        }
    }

    float oAcc[8][4];
    #pragma unroll
    for (int j = 0; j < 8; j++)
        #pragma unroll
        for (int q = 0; q < 4; q++) oAcc[j][q] = 0.f;
    float m0 = -1e30f, m1 = -1e30f, l0 = 0.f, l1 = 0.f;

    int t0g = q0 + wrow + gid, t1g = t0g + 8;
    int nTiles = q0 / FBS + 2;

    for (int it = 0; it < nTiles; it++) {
        int s0 = it * FBS;
        __syncthreads();
        #pragma unroll
        for (int i = 0; i < 4; i++) {
            int f4 = tid + i * 256;
            int r = f4 >> 4, kc = (f4 & 15) << 2;
            float4 kv = *reinterpret_cast<const float4*>(
                kbase + (size_t)(s0 + r) * (3 * CC) + kc);
            *reinterpret_cast<float4*>(Ks + r * KLD + kc) = kv;
            float4 vv = *reinterpret_cast<const float4*>(
                vbase + (size_t)(s0 + r) * (3 * CC) + kc);
            *reinterpret_cast<float4*>(Vs + r * VLD + kc) = vv;
        }
        __syncthreads();

        float sAcc[8][4];
        #pragma unroll
        for (int j = 0; j < 8; j++)
            #pragma unroll
            for (int q = 0; q < 4; q++) sAcc[j][q] = 0.f;
        #pragma unroll
        for (int ks = 0; ks < 8; ks++) {
            int kb = ks * 8;
            #pragma unroll
            for (int j = 0; j < 8; j++) {
                int n = j * 8 + gid;
                uint32_t bb[2];
                bb[0] = __float_as_uint(Ks[n * KLD + kb + tig]);
                bb[1] = __float_as_uint(Ks[n * KLD + kb + tig + 4]);
                mma8(sAcc[j], aQ[ks], bb);
            }
        }

        #pragma unroll
        for (int j = 0; j < 8; j++) {
            int sb = s0 + j * 8 + tig * 2;
            #pragma unroll
            for (int q = 0; q < 4; q++) {
                float v = sAcc[j][q] * 0.125f;
                int s_g = sb + (q & 1);
                int t_g = (q < 2) ? t0g : t1g;
                sAcc[j][q] = (s_g > t_g) ? -1e30f : v;
            }
        }

        float rm0 = -1e30f, rm1 = -1e30f;
        #pragma unroll
        for (int j = 0; j < 8; j++) {
            rm0 = fmaxf(rm0, fmaxf(sAcc[j][0], sAcc[j][1]));
            rm1 = fmaxf(rm1, fmaxf(sAcc[j][2], sAcc[j][3]));
        }
        #pragma unroll
        for (int o = 1; o <= 2; o <<= 1) {
            rm0 = fmaxf(rm0, __shfl_xor_sync(0xffffffffu, rm0, o));
            rm1 = fmaxf(rm1, __shfl_xor_sync(0xffffffffu, rm1, o));
        }
        float nm0 = fmaxf(m0, rm0), nm1 = fmaxf(m1, rm1);
        float a0 = __expf(m0 - nm0), a1 = __expf(m1 - nm1);

        float rs0 = 0.f, rs1 = 0.f;
        #pragma unroll
        for (int j = 0; j < 8; j++) {
            int sb = (j * 8 + tig * 2) * PLD;
            float p0 = __expf(sAcc[j][0] - nm0);
            float p1 = __expf(sAcc[j][1] - nm0);
            float p2 = __expf(sAcc[j][2] - nm1);
            float p3 = __expf(sAcc[j][3] - nm1);
            rs0 += p0 + p1; rs1 += p2 + p3;
            int tc0 = wrow + gid, tc1 = tc0 + 8;
            Ps[sb       + tc0] = tf32r(p0);
            Ps[sb + PLD + tc0] = tf32r(p1);
            Ps[sb       + tc1] = tf32r(p2);
            Ps[sb + PLD + tc1] = tf32r(p3);
        }
        #pragma unroll
        for (int o = 1; o <= 2; o <<= 1) {
            rs0 += __shfl_xor_sync(0xffffffffu, rs0, o);
            rs1 += __shfl_xor_sync(0xffffffffu, rs1, o);
        }
        l0 = l0 * a0 + rs0;
        l1 = l1 * a1 + rs1;
        m0 = nm0; m1 = nm1;

        #pragma unroll
        for (int j = 0; j < 8; j++) {
            oAcc[j][0] *= a0; oAcc[j][1] *= a0;
            oAcc[j][2] *= a1; oAcc[j][3] *= a1;
        }
        __syncwarp();

        #pragma unroll
        for (int ks = 0; ks < 8; ks++) {
            int kb = ks * 8;
            uint32_t aP[4];
            int mr = wrow + gid;
            aP[0] = __float_as_uint(Ps[(kb + tig    ) * PLD + mr    ]);
            aP[1] = __float_as_uint(Ps[(kb + tig    ) * PLD + mr + 8]);
            aP[2] = __float_as_uint(Ps[(kb + tig + 4) * PLD + mr    ]);
            aP[3] = __float_as_uint(Ps[(kb + tig + 4) * PLD + mr + 8]);
            #pragma unroll
            for (int j = 0; j < 8; j++) {
                int n = j * 8 + gid;
                uint32_t bb[2];
                bb[0] = __float_as_uint(Vs[(kb + tig    ) * VLD + n]);
                bb[1] = __float_as_uint(Vs[(kb + tig + 4) * VLD + n]);
                mma8(oAcc[j], aP, bb);
            }
        }
    }

    float inv0 = 1.f / l0, inv1 = 1.f / l1;
    float* o0 = outp + (size_t)(b * TT + t0g) * CC + h * HDIM;
    float* o1 = outp + (size_t)(b * TT + t1g) * CC + h * HDIM;
    #pragma unroll
    for (int j = 0; j < 8; j++) {
        int d = j * 8 + tig * 2;
        o0[d]     = tf32r(oAcc[j][0] * inv0);
        o0[d + 1] = tf32r(oAcc[j][1] * inv0);
        o1[d]     = tf32r(oAcc[j][2] * inv1);
        o1[d + 1] = tf32r(oAcc[j][3] * inv1);
    }
}

// ---------------- loss: single-pass online logsumexp (alignment-safe) --------
__global__ void zero_loss_kernel() { g_loss = 0.f; }

__global__ void loss_kernel(const float* __restrict__ logits,
                            const int* __restrict__ target) {
    int row = blockIdx.x, tid = threadIdx.x;
    const float* lr = logits + (size_t)row * VV;
    float m = -1e30f, s = 0.f;

    int head = (int)(((16u - ((uintptr_t)lr & 15u)) & 15u) >> 2);
    if (head > VV) head = VV;
    for (int i = tid; i < head; i += 256) {
        float v = lr[i];
        if (v > m) { s = s * __expf(m - v); m = v; }
        s += __expf(v - m);
    }
    const float* lra = lr + head;
    int nrem = VV - head;
    int n4 = nrem >> 2;
    for (int i4 = tid; i4 < n4; i4 += 256) {
        float4 v = *reinterpret_cast<const float4*>(lra + i4 * 4);
        float vm = fmaxf(fmaxf(v.x, v.y), fmaxf(v.z, v.w));
        if (vm > m) { s = s * __expf(m - vm); m = vm; }
        s += __expf(v.x - m) + __expf(v.y - m) + __expf(v.z - m) + __expf(v.w - m);
    }
    for (int i = head + n4 * 4 + tid; i < VV; i += 256) {
        float v = lr[i];
        if (v > m) { s = s * __expf(m - v); m = v; }
        s += __expf(v - m);
    }
    #pragma unroll
    for (int o = 16; o; o >>= 1) {
        float mo = __shfl_xor_sync(0xffffffffu, m, o);
        float so = __shfl_xor_sync(0xffffffffu, s, o);
        float M = fmaxf(m, mo);
        s = s * __expf(m - M) + so * __expf(mo - M);
        m = M;
    }
    __shared__ float rm[8], rs[8];
    if ((tid & 31) == 0) { rm[tid >> 5] = m; rs[tid >> 5] = s; }
    __syncthreads();
    if (tid == 0) {
        float M = rm[0];
        #pragma unroll
        for (int i = 1; i < 8; i++) M = fmaxf(M, rm[i]);
        float S = 0.f;
        #pragma unroll
        for (int i = 0; i < 8; i++) S += rs[i] * __expf(rm[i] - M);
        float lse = M + logf(S);
        atomicAdd(&g_loss, lse - lr[target[row]]);
    }
}

__global__ void finalize_loss_kernel(float* __restrict__ out) {
    out[(size_t)BT * VV] = g_loss * (1.0f / BT);
}

// ---------------- launch ------------------------------------------------------
extern "C" void kernel_launch(void* const* d_in, const int* in_sizes, int n_in,
                              void* d_out, int out_size) {
    const int*   x      = (const int*)  d_in[0];
    const int*   target = (const int*)  d_in[1];
    const float* tok    = (const float*)d_in[2];
    const float* pos    = (const float*)d_in[3];
    const float* ln1s   = (const float*)d_in[4];
    const float* ln1b   = (const float*)d_in[5];
    const float* wq     = (const float*)d_in[6];
    const float* wk     = (const float*)d_in[7];
    const float* wv     = (const float*)d_in[8];
    const float* wproj  = (const float*)d_in[9];
    const float* bproj  = (const float*)d_in[10];
    const float* ln2s   = (const float*)d_in[11];
    const float* ln2b   = (const float*)d_in[12];
    const float* wff1   = (const float*)d_in[13];
    const float* bff1   = (const float*)d_in[14];
    const float* wff2   = (const float*)d_in[15];
    const float* bff2   = (const float*)d_in[16];
    const float* lnfs   = (const float*)d_in[17];
    const float* lnfb   = (const float*)d_in[18];
    const float* lmw    = (const float*)d_in[19];
    const float* lmb    = (const float*)d_in[20];
    float* out = (float*)d_out;

    float *p_h, *p_ain, *p_qkv, *p_attn, *p_ff, *p_wqkv, *p_wp, *p_w1, *p_w2,
          *p_lmw;
    cudaGetSymbolAddress((void**)&p_h,    g_h);
    cudaGetSymbolAddress((void**)&p_ain,  g_ain);
    cudaGetSymbolAddress((void**)&p_qkv,  g_qkv);
    cudaGetSymbolAddress((void**)&p_attn, g_attn);
    cudaGetSymbolAddress((void**)&p_ff,   g_ff);
    cudaGetSymbolAddress((void**)&p_wqkv, g_wqkv);
    cudaGetSymbolAddress((void**)&p_wp,   g_wp);
    cudaGetSymbolAddress((void**)&p_w1,   g_w1);
    cudaGetSymbolAddress((void**)&p_w2,   g_w2);
    cudaGetSymbolAddress((void**)&p_lmw,  g_lmw);

    static int attr_done = 0;
    if (!attr_done) {
        cudaFuncSetAttribute(flash_kernel,
                             cudaFuncAttributeMaxDynamicSharedMemorySize, FSMEM);
        cudaFuncSetAttribute(gemm_tf32_kernel,
                             cudaFuncAttributeMaxDynamicSharedMemorySize, GSMEM);
        attr_done = 1;
    }

    weight_prep_kernel<<<(int)((NPREP + 255) / 256), 256>>>(
        wq, wk, wv, wproj, wff1, wff2, lmw);
    embed_kernel<<<(BT * CC + 255) / 256, 256>>>(x, tok, pos);

    dim3 gQKV((3 * CC) / 128, BT / 128);
    dim3 gC  (CC / 128,       BT / 128);
    dim3 gFF (FFD / 128,      BT / 128);
    dim3 gV  (VPAD / 128,     BT / 128);
    dim3 gFA (TT / FBQ, BHZ);

    for (int l = 0; l < LLAY; l++) {
        ln_kernel<<<BT, 256>>>(p_h, ln1s + l * CC, ln1b + l * CC, p_ain);
        gemm_tf32_kernel<<<gQKV, 256, GSMEM>>>(
            p_ain, p_wqkv + (size_t)l * CC * 3 * CC, p_qkv,
            BT, 3 * CC, CC, 3 * CC, nullptr, nullptr, 0, 1);
        flash_kernel<<<gFA, 256, FSMEM>>>(p_qkv, p_attn);
        gemm_tf32_kernel<<<gC, 256, GSMEM>>>(
            p_attn, p_wp + (size_t)l * CC * CC, p_h,
            BT, CC, CC, CC, bproj + l * CC, p_h, 0, 0);
        ln_kernel<<<BT, 256>>>(p_h, ln2s + l * CC, ln2b + l * CC, p_ain);
        gemm_tf32_kernel<<<gFF, 256, GSMEM>>>(
            p_ain, p_w1 + (size_t)l * CC * FFD, p_ff,
            BT, FFD, CC, FFD, bff1 + l * FFD, nullptr, 1, 1);
        gemm_tf32_kernel<<<gC, 256, GSMEM>>>(
            p_ff, p_w2 + (size_t)l * FFD * CC, p_h,
            BT, CC, FFD, CC, bff2 + l * CC, p_h, 0, 0);
    }

    ln_kernel<<<BT, 256>>>(p_h, lnfs, lnfb, p_ain);
    gemm_tf32_kernel<<<gV, 256, GSMEM>>>(
        p_ain, p_lmw, out, BT, VV, CC, VPAD, lmb, nullptr, 0, 0);

    if ((long long)out_size > (long long)BT * VV) {
        zero_loss_kernel<<<1, 1>>>();
        loss_kernel<<<BT, 256>>>(out, target);
        finalize_loss_kernel<<<1, 1>>>(out);
    }
}

// round 10
// speedup vs baseline: 1.0267x; 1.0251x over previous
#include <cuda_runtime.h>
#include <cuda_fp16.h>
#include <math.h>
#include <stdint.h>

#define BATCH 2
#define TT    2048
#define BT    4096
#define CC    512
#define HH    8
#define HDIM  64
#define LLAY  4
#define VV    50257
#define VPAD  50304               // multiple of 128
#define FFD   2048
#define LNEPS 1e-5f
#define BHZ   16

// ---------------- scratch -----------------------------------------------------
__device__ float  g_h    [BT*CC];
__device__ __half g_ainh [BT*CC];                  // ln outputs (GEMM A)
__device__ float  g_qkv  [BT*3*CC];                // flash input (fp32)
__device__ __half g_attnh[BT*CC];                  // flash output (GEMM A)
__device__ __half g_ffh  [(size_t)BT*FFD];         // ff1 output (GEMM A)
__device__ __half g_wqkvT[(size_t)LLAY*3*CC*CC];   // [l][n=3C][k=C]
__device__ __half g_wpT  [(size_t)LLAY*CC*CC];
__device__ __half g_w1T  [(size_t)LLAY*FFD*CC];
__device__ __half g_w2T  [(size_t)LLAY*CC*FFD];
__device__ __half g_lmwT [(size_t)VPAD*CC];        // [v][c] padded
__device__ float  g_loss;

// ---------------- helpers ------------------------------------------------------
__device__ __forceinline__ float warpSum(float v) {
    #pragma unroll
    for (int o = 16; o; o >>= 1) v += __shfl_xor_sync(0xffffffffu, v, o);
    return v;
}
__device__ __forceinline__ float tf32r(float x) {
    uint32_t u;
    asm("cvt.rna.tf32.f32 %0, %1;" : "=r"(u) : "f"(x));
    return __uint_as_float(u);
}
// tf32 mma (flash kernel)
__device__ __forceinline__ void mma8(float* c, const uint32_t* a, const uint32_t* b) {
    asm volatile(
        "mma.sync.aligned.m16n8k8.row.col.f32.tf32.tf32.f32 "
        "{%0,%1,%2,%3}, {%4,%5,%6,%7}, {%8,%9}, {%0,%1,%2,%3};"
        : "+f"(c[0]), "+f"(c[1]), "+f"(c[2]), "+f"(c[3])
        : "r"(a[0]), "r"(a[1]), "r"(a[2]), "r"(a[3]), "r"(b[0]), "r"(b[1]));
}
// fp16 mma (GEMMs)
__device__ __forceinline__ void mma16(float* c, const uint32_t* a, const uint32_t* b) {
    asm volatile(
        "mma.sync.aligned.m16n8k16.row.col.f32.f16.f16.f32 "
        "{%0,%1,%2,%3}, {%4,%5,%6,%7}, {%8,%9}, {%0,%1,%2,%3};"
        : "+f"(c[0]), "+f"(c[1]), "+f"(c[2]), "+f"(c[3])
        : "r"(a[0]), "r"(a[1]), "r"(a[2]), "r"(a[3]), "r"(b[0]), "r"(b[1]));
}
__device__ __forceinline__ uint32_t sptr(const void* p) {
    return (uint32_t)__cvta_generic_to_shared(p);
}
#define CP_ASYNC16(d, s) \
    asm volatile("cp.async.ca.shared.global [%0], [%1], 16;\n" :: "r"(d), "l"(s))
#define CP_COMMIT() asm volatile("cp.async.commit_group;\n" ::: "memory")
#define CP_WAIT1()  asm volatile("cp.async.wait_group 1;\n"  ::: "memory")

// ---------------- weight transposes (→ half) ----------------------------------
// dst[n][k] = half(src[k][n]); grid x=n-tiles, y=k-tiles, z=slabs
__global__ void wtrans_kernel(__half* __restrict__ dst, const float* __restrict__ src,
                              int R, int Creal, long long sStride, long long dStride) {
    __shared__ float t[32][33];
    const float* s = src + (size_t)blockIdx.z * sStride;
    __half* d = dst + (size_t)blockIdx.z * dStride;
    int c0 = blockIdx.x * 32, r0 = blockIdx.y * 32;
    int tx = threadIdx.x, ty = threadIdx.y;
    #pragma unroll
    for (int i = 0; i < 32; i += 8) {
        int c = c0 + tx;
        t[tx][ty + i] = (c < Creal) ? s[(size_t)(r0 + ty + i) * Creal + c] : 0.f;
    }
    __syncthreads();
    #pragma unroll
    for (int i = 0; i < 32; i += 8)
        d[(size_t)(c0 + ty + i) * R + r0 + tx] = __float2half_rn(t[ty + i][tx]);
}

// packed QKV: dst[l][j=(which,h,d)][c]
__global__ void qkvtrans_kernel(const float* __restrict__ wq,
                                const float* __restrict__ wk,
                                const float* __restrict__ wv) {
    __shared__ float t[32][33];
    int l = blockIdx.z;
    int j0 = blockIdx.x * 32, c0 = blockIdx.y * 32;
    int which = j0 >> 9, h = (j0 & 511) >> 6, d0 = j0 & 63;
    const float* w = (which == 0) ? wq : (which == 1) ? wk : wv;
    const float* s = w + (((size_t)l * HH + h) * CC) * HDIM;
    int tx = threadIdx.x, ty = threadIdx.y;
    #pragma unroll
    for (int i = 0; i < 32; i += 8)
        t[tx][ty + i] = s[(size_t)(c0 + ty + i) * HDIM + d0 + tx];
    __syncthreads();
    __half* d = g_wqkvT + ((size_t)l * (3 * CC) + j0) * CC + c0;
    #pragma unroll
    for (int i = 0; i < 32; i += 8)
        d[(size_t)(ty + i) * CC + tx] = __float2half_rn(t[ty + i][tx]);
}

// ---------------- embedding / layernorm ---------------------------------------
__global__ void embed_kernel(const int* __restrict__ x, const float* __restrict__ tok,
                             const float* __restrict__ pos) {
    int i = blockIdx.x * blockDim.x + threadIdx.x;
    if (i >= BT * CC) return;
    int c = i % CC, bt = i / CC, t = bt % TT;
    g_h[i] = tok[(size_t)x[bt] * CC + c] + pos[(size_t)t * CC + c];
}

__global__ void ln_kernel(const float* __restrict__ in, const float* __restrict__ sc,
                          const float* __restrict__ bi, __half* __restrict__ out) {
    int row = blockIdx.x, tid = threadIdx.x;
    const float* r = in + (size_t)row * CC;
    float a = r[tid], b = r[tid + 256];
    float s = a + b, q = a * a + b * b;
    s = warpSum(s); q = warpSum(q);
    __shared__ float rs[8], rq[8];
    if ((tid & 31) == 0) { rs[tid >> 5] = s; rq[tid >> 5] = q; }
    __syncthreads();
    __shared__ float s_mean, s_rstd;
    if (tid == 0) {
        float S = 0.f, Q = 0.f;
        #pragma unroll
        for (int i = 0; i < 8; i++) { S += rs[i]; Q += rq[i]; }
        float m = S * (1.0f / CC);
        s_mean = m; s_rstd = rsqrtf(Q * (1.0f / CC) - m * m + LNEPS);
    }
    __syncthreads();
    float m = s_mean, rstd = s_rstd;
    __half* o = out + (size_t)row * CC;
    o[tid]       = __float2half_rn((a - m) * rstd * sc[tid]       + bi[tid]);
    o[tid + 256] = __float2half_rn((b - m) * rstd * sc[tid + 256] + bi[tid + 256]);
}

// ---------------- fp16 GEMM: C[M,N] = A[M,K] @ Bt[N,K]^T ----------------------
// 128x128 tile, BK=32 halves, 256 thr (8 warps 2x4, 64x32 each), 3-stage cp.async.
#define ALD 40                       // halves stride (80B rows)
#define STGB 20480                   // bytes per stage (A 10240 + B 10240)
#define HSMEM (3*STGB)               // 61440

__global__ __launch_bounds__(256, 3)
void gemm_fp16_kernel(const __half* __restrict__ A, const __half* __restrict__ Bt,
                      float* __restrict__ Cout, __half* __restrict__ CoutH,
                      int Nreal, int K,
                      const float* __restrict__ bias, const float* __restrict__ res,
                      int relu, int rnd) {
    extern __shared__ __align__(16) char hsm[];
    int tid = threadIdx.x;
    int row0 = blockIdx.y << 7, col0 = blockIdx.x << 7;
    int lane = tid & 31, gid = lane >> 2, tig = lane & 3;
    int wid = tid >> 5;
    int wr = (wid >> 2) * 64;
    int wc = (wid & 3) * 32;

    float acc[4][4][4];
    #pragma unroll
    for (int i = 0; i < 4; i++)
        #pragma unroll
        for (int j = 0; j < 4; j++)
            #pragma unroll
            for (int q = 0; q < 4; q++) acc[i][j][q] = 0.f;

    const __half* Ab = A + (size_t)row0 * K;
    const __half* Bb = Bt + (size_t)col0 * K;

    int r0 = tid >> 2, c0 = tid & 3;
    int r1 = (tid + 256) >> 2, c1 = (tid + 256) & 3;

    #define LOAD_STAGE(st, k0)                                                 \
        do {                                                                   \
            uint32_t as = sptr(hsm) + (st) * STGB;                             \
            uint32_t bs = as + 10240;                                          \
            CP_ASYNC16(as + r0 * 80 + c0 * 16, Ab + (size_t)r0 * K + (k0) + c0 * 8); \
            CP_ASYNC16(as + r1 * 80 + c1 * 16, Ab + (size_t)r1 * K + (k0) + c1 * 8); \
            CP_ASYNC16(bs + r0 * 80 + c0 * 16, Bb + (size_t)r0 * K + (k0) + c0 * 8); \
            CP_ASYNC16(bs + r1 * 80 + c1 * 16, Bb + (size_t)r1 * K + (k0) + c1 * 8); \
        } while (0)

    int ntiles = K >> 5;
    LOAD_STAGE(0, 0);  CP_COMMIT();
    if (ntiles > 1) LOAD_STAGE(1, 32);
    CP_COMMIT();

    int st = 0;
    for (int it = 0; it < ntiles; it++) {
        CP_WAIT1();
        __syncthreads();
        int nx = it + 2;
        int stn = st + 2; if (stn >= 3) stn -= 3;
        if (nx < ntiles) LOAD_STAGE(stn, nx << 5);
        CP_COMMIT();

        const __half* as = (const __half*)(hsm + st * STGB);
        const __half* bs = as + 5120;
        #pragma unroll
        for (int ks = 0; ks < 2; ks++) {
            int kb = ks << 4;
            uint32_t af[4][4], bf[4][2];
            #pragma unroll
            for (int i = 0; i < 4; i++) {
                int m = wr + i * 16 + gid;
                af[i][0] = *(const uint32_t*)&as[(m    ) * ALD + kb + 2 * tig    ];
                af[i][1] = *(const uint32_t*)&as[(m + 8) * ALD + kb + 2 * tig    ];
                af[i][2] = *(const uint32_t*)&as[(m    ) * ALD + kb + 2 * tig + 8];
                af[i][3] = *(const uint32_t*)&as[(m + 8) * ALD + kb + 2 * tig + 8];
            }
            #pragma unroll
            for (int j = 0; j < 4; j++) {
                int n = wc + j * 8 + gid;
                bf[j][0] = *(const uint32_t*)&bs[n * ALD + kb + 2 * tig    ];
                bf[j][1] = *(const uint32_t*)&bs[n * ALD + kb + 2 * tig + 8];
            }
            #pragma unroll
            for (int i = 0; i < 4; i++)
                #pragma unroll
                for (int j = 0; j < 4; j++)
                    mma16(acc[i][j], af[i], bf[j]);
        }
        if (++st == 3) st = 0;
    }
    #undef LOAD_STAGE

    #pragma unroll
    for (int i = 0; i < 4; i++)
        #pragma unroll
        for (int j = 0; j < 4; j++) {
            int cc0 = col0 + wc + j * 8 + tig * 2;
            #pragma unroll
            for (int h2 = 0; h2 < 2; h2++) {
                int r = row0 + wr + i * 16 + gid + h2 * 8;
                float v0 = acc[i][j][h2 * 2 + 0];
                float v1 = acc[i][j][h2 * 2 + 1];
                if (cc0 < Nreal) {
                    if (bias) v0 += bias[cc0];
                    if (res)  v0 += res[(size_t)r * Nreal + cc0];
                    if (relu) v0 = fmaxf(v0, 0.f);
                    if (CoutH) CoutH[(size_t)r * Nreal + cc0] = __float2half_rn(v0);
                    else       Cout [(size_t)r * Nreal + cc0] = rnd ? tf32r(v0) : v0;
                }
                if (cc0 + 1 < Nreal) {
                    if (bias) v1 += bias[cc0 + 1];
                    if (res)  v1 += res[(size_t)r * Nreal + cc0 + 1];
                    if (relu) v1 = fmaxf(v1, 0.f);
                    if (CoutH) CoutH[(size_t)r * Nreal + cc0 + 1] = __float2half_rn(v1);
                    else       Cout [(size_t)r * Nreal + cc0 + 1] = rnd ? tf32r(v1) : v1;
                }
            }
        }
}

// ---------------- fused flash attention (tf32 mma, half output) ---------------
#define FBQ 128
#define FBS 64
#define KLD 68
#define VLD 72
#define PLD 136
#define FSMEM ((FBS*KLD + FBS*VLD + FBS*PLD) * 4)

__global__ __launch_bounds__(256, 1)
void flash_kernel(const float* __restrict__ qkv, __half* __restrict__ outp) {
    extern __shared__ float fsm[];
    float* Ks = fsm;
    float* Vs = fsm + FBS * KLD;
    float* Ps = fsm + FBS * (KLD + VLD);

    int tid = threadIdx.x;
    int lane = tid & 31, gid = lane >> 2, tig = lane & 3;
    int wid = tid >> 5;
    int wrow = wid * 16;
    int q0 = (gridDim.x - 1 - blockIdx.x) * FBQ;
    int z = blockIdx.y;
    int b = z >> 3, h = z & 7;
    const float* qbase = qkv + (size_t)b * TT * (3 * CC) + h * HDIM;
    const float* kbase = qbase + CC;
    const float* vbase = qbase + 2 * CC;

    uint32_t aQ[8][4];
    {
        int t0 = q0 + wrow + gid;
        const float* q0p = qbase + (size_t)t0 * (3 * CC);
        const float* q1p = q0p + 8 * (3 * CC);
        #pragma unroll
        for (int ks = 0; ks < 8; ks++) {
            aQ[ks][0] = __float_as_uint(q0p[ks * 8 + tig]);
            aQ[ks][1] = __float_as_uint(q1p[ks * 8 + tig]);
            aQ[ks][2] = __float_as_uint(q0p[ks * 8 + tig + 4]);
            aQ[ks][3] = __float_as_uint(q1p[ks * 8 + tig + 4]);
        }
    }
    float oAcc[8][4];
    #pragma unroll
    for (int j = 0; j < 8; j++)
        #pragma unroll
        for (int q = 0; q < 4; q++) oAcc[j][q] = 0.f;
    float m0 = -1e30f, m1 = -1e30f, l0 = 0.f, l1 = 0.f;
    int t0g = q0 + wrow + gid, t1g = t0g + 8;
    int nTiles = q0 / FBS + 2;

    for (int it = 0; it < nTiles; it++) {
        int s0 = it * FBS;
        __syncthreads();
        #pragma unroll
        for (int i = 0; i < 4; i++) {
            int f4 = tid + i * 256;
            int r = f4 >> 4, kc = (f4 & 15) << 2;
            float4 kv = *reinterpret_cast<const float4*>(
                kbase + (size_t)(s0 + r) * (3 * CC) + kc);
            *reinterpret_cast<float4*>(Ks + r * KLD + kc) = kv;
            float4 vv = *reinterpret_cast<const float4*>(
                vbase + (size_t)(s0 + r) * (3 * CC) + kc);
            *reinterpret_cast<float4*>(Vs + r * VLD + kc) = vv;
        }
        __syncthreads();

        float sAcc[8][4];
        #pragma unroll
        for (int j = 0; j < 8; j++)
            #pragma unroll
            for (int q = 0; q < 4; q++) sAcc[j][q] = 0.f;
        #pragma unroll
        for (int ks = 0; ks < 8; ks++) {
            int kb = ks * 8;
            #pragma unroll
            for (int j = 0; j < 8; j++) {
                int n = j * 8 + gid;
                uint32_t bb[2];
                bb[0] = __float_as_uint(Ks[n * KLD + kb + tig]);
                bb[1] = __float_as_uint(Ks[n * KLD + kb + tig + 4]);
                mma8(sAcc[j], aQ[ks], bb);
            }
        }
        #pragma unroll
        for (int j = 0; j < 8; j++) {
            int sb = s0 + j * 8 + tig * 2;
            #pragma unroll
            for (int q = 0; q < 4; q++) {
                float v = sAcc[j][q] * 0.125f;
                int s_g = sb + (q & 1);
                int t_g = (q < 2) ? t0g : t1g;
                sAcc[j][q] = (s_g > t_g) ? -1e30f : v;
            }
        }
        float rm0 = -1e30f, rm1 = -1e30f;
        #pragma unroll
        for (int j = 0; j < 8; j++) {
            rm0 = fmaxf(rm0, fmaxf(sAcc[j][0], sAcc[j][1]));
            rm1 = fmaxf(rm1, fmaxf(sAcc[j][2], sAcc[j][3]));
        }
        #pragma unroll
        for (int o = 1; o <= 2; o <<= 1) {
            rm0 = fmaxf(rm0, __shfl_xor_sync(0xffffffffu, rm0, o));
            rm1 = fmaxf(rm1, __shfl_xor_sync(0xffffffffu, rm1, o));
        }
        float nm0 = fmaxf(m0, rm0), nm1 = fmaxf(m1, rm1);
        float a0 = __expf(m0 - nm0), a1 = __expf(m1 - nm1);
        float rs0 = 0.f, rs1 = 0.f;
        #pragma unroll
        for (int j = 0; j < 8; j++) {
            int sb = (j * 8 + tig * 2) * PLD;
            float p0 = __expf(sAcc[j][0] - nm0);
            float p1 = __expf(sAcc[j][1] - nm0);
            float p2 = __expf(sAcc[j][2] - nm1);
            float p3 = __expf(sAcc[j][3] - nm1);
            rs0 += p0 + p1; rs1 += p2 + p3;
            int tc0 = wrow + gid, tc1 = tc0 + 8;
            Ps[sb       + tc0] = tf32r(p0);
            Ps[sb + PLD + tc0] = tf32r(p1);
            Ps[sb       + tc1] = tf32r(p2);
            Ps[sb + PLD + tc1] = tf32r(p3);
        }
        #pragma unroll
        for (int o = 1; o <= 2; o <<= 1) {
            rs0 += __shfl_xor_sync(0xffffffffu, rs0, o);
            rs1 += __shfl_xor_sync(0xffffffffu, rs1, o);
        }
        l0 = l0 * a0 + rs0;
        l1 = l1 * a1 + rs1;
        m0 = nm0; m1 = nm1;
        #pragma unroll
        for (int j = 0; j < 8; j++) {
            oAcc[j][0] *= a0; oAcc[j][1] *= a0;
            oAcc[j][2] *= a1; oAcc[j][3] *= a1;
        }
        __syncwarp();
        #pragma unroll
        for (int ks = 0; ks < 8; ks++) {
            int kb = ks * 8;
            uint32_t aP[4];
            int mr = wrow + gid;
            aP[0] = __float_as_uint(Ps[(kb + tig    ) * PLD + mr    ]);
            aP[1] = __float_as_uint(Ps[(kb + tig    ) * PLD + mr + 8]);
            aP[2] = __float_as_uint(Ps[(kb + tig + 4) * PLD + mr    ]);
            aP[3] = __float_as_uint(Ps[(kb + tig + 4) * PLD + mr + 8]);
            #pragma unroll
            for (int j = 0; j < 8; j++) {
                int n = j * 8 + gid;
                uint32_t bb[2];
                bb[0] = __float_as_uint(Vs[(kb + tig    ) * VLD + n]);
                bb[1] = __float_as_uint(Vs[(kb + tig + 4) * VLD + n]);
                mma8(oAcc[j], aP, bb);
            }
        }
    }
    float inv0 = 1.f / l0, inv1 = 1.f / l1;
    __half* o0 = outp + (size_t)(b * TT + t0g) * CC + h * HDIM;
    __half* o1 = outp + (size_t)(b * TT + t1g) * CC + h * HDIM;
    #pragma unroll
    for (int j = 0; j < 8; j++) {
        int d = j * 8 + tig * 2;
        o0[d]     = __float2half_rn(oAcc[j][0] * inv0);
        o0[d + 1] = __float2half_rn(oAcc[j][1] * inv0);
        o1[d]     = __float2half_rn(oAcc[j][2] * inv1);
        o1[d + 1] = __float2half_rn(oAcc[j][3] * inv1);
    }
}

// ---------------- loss ---------------------------------------------------------
__global__ void zero_loss_kernel() { g_loss = 0.f; }

__global__ void loss_kernel(const float* __restrict__ logits,
                            const int* __restrict__ target) {
    int row = blockIdx.x, tid = threadIdx.x;
    const float* lr = logits + (size_t)row * VV;
    float m = -1e30f, s = 0.f;
    int head = (int)(((16u - ((uintptr_t)lr & 15u)) & 15u) >> 2);
    if (head > VV) head = VV;
    for (int i = tid; i < head; i += 256) {
        float v = lr[i];
        if (v > m) { s = s * __expf(m - v); m = v; }
        s += __expf(v - m);
    }
    const float* lra = lr + head;
    int n4 = (VV - head) >> 2;
    for (int i4 = tid; i4 < n4; i4 += 256) {
        float4 v = *reinterpret_cast<const float4*>(lra + i4 * 4);
        float vm = fmaxf(fmaxf(v.x, v.y), fmaxf(v.z, v.w));
        if (vm > m) { s = s * __expf(m - vm); m = vm; }
        s += __expf(v.x - m) + __expf(v.y - m) + __expf(v.z - m) + __expf(v.w - m);
    }
    for (int i = head + n4 * 4 + tid; i < VV; i += 256) {
        float v = lr[i];
        if (v > m) { s = s * __expf(m - v); m = v; }
        s += __expf(v - m);
    }
    #pragma unroll
    for (int o = 16; o; o >>= 1) {
        float mo = __shfl_xor_sync(0xffffffffu, m, o);
        float so = __shfl_xor_sync(0xffffffffu, s, o);
        float M = fmaxf(m, mo);
        s = s * __expf(m - M) + so * __expf(mo - M);
        m = M;
    }
    __shared__ float rm[8], rs[8];
    if ((tid & 31) == 0) { rm[tid >> 5] = m; rs[tid >> 5] = s; }
    __syncthreads();
    if (tid == 0) {
        float M = rm[0];
        #pragma unroll
        for (int i = 1; i < 8; i++) M = fmaxf(M, rm[i]);
        float S = 0.f;
        #pragma unroll
        for (int i = 0; i < 8; i++) S += rs[i] * __expf(rm[i] - M);
        atomicAdd(&g_loss, M + logf(S) - lr[target[row]]);
    }
}

__global__ void finalize_loss_kernel(float* __restrict__ out) {
    out[(size_t)BT * VV] = g_loss * (1.0f / BT);
}

// ---------------- launch ------------------------------------------------------
extern "C" void kernel_launch(void* const* d_in, const int* in_sizes, int n_in,
                              void* d_out, int out_size) {
    const int*   x      = (const int*)  d_in[0];
    const int*   target = (const int*)  d_in[1];
    const float* tok    = (const float*)d_in[2];
    const float* pos    = (const float*)d_in[3];
    const float* ln1s   = (const float*)d_in[4];
    const float* ln1b   = (const float*)d_in[5];
    const float* wq     = (const float*)d_in[6];
    const float* wk     = (const float*)d_in[7];
    const float* wv     = (const float*)d_in[8];
    const float* wproj  = (const float*)d_in[9];
    const float* bproj  = (const float*)d_in[10];
    const float* ln2s   = (const float*)d_in[11];
    const float* ln2b   = (const float*)d_in[12];
    const float* wff1   = (const float*)d_in[13];
    const float* bff1   = (const float*)d_in[14];
    const float* wff2   = (const float*)d_in[15];
    const float* bff2   = (const float*)d_in[16];
    const float* lnfs   = (const float*)d_in[17];
    const float* lnfb   = (const float*)d_in[18];
    const float* lmw    = (const float*)d_in[19];
    const float* lmb    = (const float*)d_in[20];
    float* out = (float*)d_out;

    float  *p_h, *p_qkv;
    __half *p_ainh, *p_attnh, *p_ffh, *p_wqkvT, *p_wpT, *p_w1T, *p_w2T, *p_lmwT;
    cudaGetSymbolAddress((void**)&p_h,     g_h);
    cudaGetSymbolAddress((void**)&p_qkv,   g_qkv);
    cudaGetSymbolAddress((void**)&p_ainh,  g_ainh);
    cudaGetSymbolAddress((void**)&p_attnh, g_attnh);
    cudaGetSymbolAddress((void**)&p_ffh,   g_ffh);
    cudaGetSymbolAddress((void**)&p_wqkvT, g_wqkvT);
    cudaGetSymbolAddress((void**)&p_wpT,   g_wpT);
    cudaGetSymbolAddress((void**)&p_w1T,   g_w1T);
    cudaGetSymbolAddress((void**)&p_w2T,   g_w2T);
    cudaGetSymbolAddress((void**)&p_lmwT,  g_lmwT);

    static int attr_done = 0;
    if (!attr_done) {
        cudaFuncSetAttribute(flash_kernel,
                             cudaFuncAttributeMaxDynamicSharedMemorySize, FSMEM);
        cudaFuncSetAttribute(gemm_fp16_kernel,
                             cudaFuncAttributeMaxDynamicSharedMemorySize, HSMEM);
        attr_done = 1;
    }

    dim3 tb(32, 8);
    qkvtrans_kernel<<<dim3(48, 16, LLAY), tb>>>(wq, wk, wv);
    wtrans_kernel<<<dim3(16, 16, LLAY), tb>>>(p_wpT, wproj, CC, CC,
                                              (long long)CC * CC, (long long)CC * CC);
    wtrans_kernel<<<dim3(64, 16, LLAY), tb>>>(p_w1T, wff1, CC, FFD,
                                              (long long)CC * FFD, (long long)FFD * CC);
    wtrans_kernel<<<dim3(16, 64, LLAY), tb>>>(p_w2T, wff2, FFD, CC,
                                              (long long)FFD * CC, (long long)CC * FFD);
    wtrans_kernel<<<dim3(VPAD / 32, 16, 1), tb>>>(p_lmwT, lmw, CC, VV, 0, 0);
    embed_kernel<<<(BT * CC + 255) / 256, 256>>>(x, tok, pos);

    dim3 gQKV(12, 32), gC2(4, 32), gFF(16, 32), gV(VPAD / 128, 32);
    dim3 gFA(TT / FBQ, BHZ);

    for (int l = 0; l < LLAY; l++) {
        ln_kernel<<<BT, 256>>>(p_h, ln1s + l * CC, ln1b + l * CC, p_ainh);
        gemm_fp16_kernel<<<gQKV, 256, HSMEM>>>(
            p_ainh, p_wqkvT + (size_t)l * 3 * CC * CC, p_qkv, nullptr,
            3 * CC, CC, nullptr, nullptr, 0, 1);
        flash_kernel<<<gFA, 256, FSMEM>>>(p_qkv, p_attnh);
        gemm_fp16_kernel<<<gC2, 256, HSMEM>>>(
            p_attnh, p_wpT + (size_t)l * CC * CC, p_h, nullptr,
            CC, CC, bproj + l * CC, p_h, 0, 0);
        ln_kernel<<<BT, 256>>>(p_h, ln2s + l * CC, ln2b + l * CC, p_ainh);
        gemm_fp16_kernel<<<gFF, 256, HSMEM>>>(
            p_ainh, p_w1T + (size_t)l * FFD * CC, nullptr, p_ffh,
            FFD, CC, bff1 + l * FFD, nullptr, 1, 0);
        gemm_fp16_kernel<<<gC2, 256, HSMEM>>>(
            p_ffh, p_w2T + (size_t)l * CC * FFD, p_h, nullptr,
            CC, FFD, bff2 + l * CC, p_h, 0, 0);
    }

    ln_kernel<<<BT, 256>>>(p_h, lnfs, lnfb, p_ainh);
    gemm_fp16_kernel<<<gV, 256, HSMEM>>>(
        p_ainh, p_lmwT, out, nullptr, VV, CC, lmb, nullptr, 0, 0);

    if ((long long)out_size > (long long)BT * VV) {
        zero_loss_kernel<<<1, 1>>>();
        loss_kernel<<<BT, 256>>>(out, target);
        finalize_loss_kernel<<<1, 1>>>(out);
    }
}